// round 1
// baseline (speedup 1.0000x reference)
#include <cuda_runtime.h>
#include <cuda_bf16.h>
#include <cstdint>

// Problem constants
// x: [4, 256, 64, 64] -> [B=4, C=256, N=4096]
// GroupNorm(8, 256); qkv 1x1 conv W[768,256]; nh=4, dh=64; proj W[256,256]; residual.

#define B_ 4
#define C_ 256
#define N_ 4096
#define G_ 8
#define CPG_ 32
#define NH_ 4
#define DH_ 64

// Scratch (device globals; no allocation allowed)
__device__ float g_h[B_ * C_ * N_];        // groupnorm output   (16 MB)
__device__ float g_qkv[B_ * 3 * C_ * N_];  // qkv conv output    (48 MB)
__device__ float g_ao[B_ * C_ * N_];       // attention output   (16 MB)

// ---------------------------------------------------------------------------
// GroupNorm: one block per (b, g). Reduce over 32 channels x 4096 = 131072.
// ---------------------------------------------------------------------------
__global__ void gn_kernel(const float* __restrict__ x,
                          const float* __restrict__ gn_w,
                          const float* __restrict__ gn_b) {
    const int total = CPG_ * N_;  // 131072
    int b = blockIdx.x >> 3, g = blockIdx.x & 7;
    const float* xp = x + (size_t)(b * C_ + g * CPG_) * N_;
    float* hp = g_h + (size_t)(b * C_ + g * CPG_) * N_;

    float s = 0.f, ss = 0.f;
    for (int i = threadIdx.x * 4; i < total; i += blockDim.x * 4) {
        float4 v = *(const float4*)(xp + i);
        s  += v.x + v.y + v.z + v.w;
        ss += v.x * v.x + v.y * v.y + v.z * v.z + v.w * v.w;
    }
#pragma unroll
    for (int o = 16; o; o >>= 1) {
        s  += __shfl_xor_sync(0xffffffffu, s, o);
        ss += __shfl_xor_sync(0xffffffffu, ss, o);
    }
    __shared__ float rs[8], rss[8];
    __shared__ float s_mu, s_rstd;
    int wid = threadIdx.x >> 5, lid = threadIdx.x & 31;
    if (lid == 0) { rs[wid] = s; rss[wid] = ss; }
    __syncthreads();
    if (threadIdx.x == 0) {
        float S = 0.f, SS = 0.f;
#pragma unroll
        for (int w = 0; w < 8; w++) { S += rs[w]; SS += rss[w]; }
        float mu = S / (float)total;
        float var = SS / (float)total - mu * mu;
        s_mu = mu;
        s_rstd = rsqrtf(var + 1e-5f);
    }
    __syncthreads();
    float mu = s_mu, rstd = s_rstd;
    for (int i = threadIdx.x * 4; i < total; i += blockDim.x * 4) {
        int c = g * CPG_ + (i >> 12);          // i / 4096
        float w = gn_w[c] * rstd;
        float bb = gn_b[c] - mu * w;
        float4 v = *(const float4*)(xp + i);
        v.x = v.x * w + bb; v.y = v.y * w + bb;
        v.z = v.z * w + bb; v.w = v.w * w + bb;
        *(float4*)(hp + i) = v;
    }
}

// ---------------------------------------------------------------------------
// QKV GEMM: g_qkv[b,o,n] = sum_c W[o,c] * g_h[b,c,n] + bias[o]
// 64x64 tile, Kc=16, 256 threads, 4x4 per thread.
// grid: (N/64, 768/64, B)
// ---------------------------------------------------------------------------
__global__ void qkv_gemm_kernel(const float* __restrict__ W,
                                const float* __restrict__ bias) {
    __shared__ float Ast[16][68];  // [kc][o]
    __shared__ float Bs[16][64];   // [kc][n]
    int b = blockIdx.z;
    int ot = blockIdx.y << 6, nt = blockIdx.x << 6;
    int tid = threadIdx.x, ty = tid >> 4, tx = tid & 15;
    const float* Hb = g_h + (size_t)b * C_ * N_;
    float acc[4][4] = {};

    for (int k0 = 0; k0 < C_; k0 += 16) {
        {
            int o = tid >> 2, c4 = (tid & 3) << 2;
            float4 w4 = *(const float4*)(W + (size_t)(ot + o) * C_ + k0 + c4);
            Ast[c4 + 0][o] = w4.x; Ast[c4 + 1][o] = w4.y;
            Ast[c4 + 2][o] = w4.z; Ast[c4 + 3][o] = w4.w;
        }
        {
            int cc = tid >> 4, n4 = (tid & 15) << 2;
            *(float4*)&Bs[cc][n4] =
                *(const float4*)(Hb + (size_t)(k0 + cc) * N_ + nt + n4);
        }
        __syncthreads();
#pragma unroll
        for (int kc = 0; kc < 16; kc++) {
            float4 a = *(float4*)&Ast[kc][ty << 2];
            float4 bv4 = *(float4*)&Bs[kc][tx << 2];
            float av[4] = {a.x, a.y, a.z, a.w};
            float bv[4] = {bv4.x, bv4.y, bv4.z, bv4.w};
#pragma unroll
            for (int ii = 0; ii < 4; ii++)
#pragma unroll
                for (int jj = 0; jj < 4; jj++) acc[ii][jj] += av[ii] * bv[jj];
        }
        __syncthreads();
    }
#pragma unroll
    for (int ii = 0; ii < 4; ii++) {
        int o = ot + (ty << 2) + ii;
        float bo = bias[o];
        float4 r = make_float4(acc[ii][0] + bo, acc[ii][1] + bo,
                               acc[ii][2] + bo, acc[ii][3] + bo);
        *(float4*)(g_qkv + ((size_t)b * 768 + o) * N_ + nt + (tx << 2)) = r;
    }
}

// ---------------------------------------------------------------------------
// Proj GEMM + bias + residual: out[b,o,n] = x[b,o,n] + bias[o] + sum_c W[o,c]*g_ao[b,c,n]
// grid: (N/64, 256/64, B)
// ---------------------------------------------------------------------------
__global__ void proj_gemm_kernel(const float* __restrict__ W,
                                 const float* __restrict__ bias,
                                 const float* __restrict__ x,
                                 float* __restrict__ out) {
    __shared__ float Ast[16][68];
    __shared__ float Bs[16][64];
    int b = blockIdx.z;
    int ot = blockIdx.y << 6, nt = blockIdx.x << 6;
    int tid = threadIdx.x, ty = tid >> 4, tx = tid & 15;
    const float* Hb = g_ao + (size_t)b * C_ * N_;
    float acc[4][4] = {};

    for (int k0 = 0; k0 < C_; k0 += 16) {
        {
            int o = tid >> 2, c4 = (tid & 3) << 2;
            float4 w4 = *(const float4*)(W + (size_t)(ot + o) * C_ + k0 + c4);
            Ast[c4 + 0][o] = w4.x; Ast[c4 + 1][o] = w4.y;
            Ast[c4 + 2][o] = w4.z; Ast[c4 + 3][o] = w4.w;
        }
        {
            int cc = tid >> 4, n4 = (tid & 15) << 2;
            *(float4*)&Bs[cc][n4] =
                *(const float4*)(Hb + (size_t)(k0 + cc) * N_ + nt + n4);
        }
        __syncthreads();
#pragma unroll
        for (int kc = 0; kc < 16; kc++) {
            float4 a = *(float4*)&Ast[kc][ty << 2];
            float4 bv4 = *(float4*)&Bs[kc][tx << 2];
            float av[4] = {a.x, a.y, a.z, a.w};
            float bv[4] = {bv4.x, bv4.y, bv4.z, bv4.w};
#pragma unroll
            for (int ii = 0; ii < 4; ii++)
#pragma unroll
                for (int jj = 0; jj < 4; jj++) acc[ii][jj] += av[ii] * bv[jj];
        }
        __syncthreads();
    }
#pragma unroll
    for (int ii = 0; ii < 4; ii++) {
        int o = ot + (ty << 2) + ii;
        float bo = bias[o];
        size_t idx = ((size_t)b * C_ + o) * N_ + nt + (tx << 2);
        float4 xr = *(const float4*)(x + idx);
        float4 r = make_float4(acc[ii][0] + bo + xr.x, acc[ii][1] + bo + xr.y,
                               acc[ii][2] + bo + xr.z, acc[ii][3] + bo + xr.w);
        *(float4*)(out + idx) = r;
    }
}

// ---------------------------------------------------------------------------
// Flash attention (fp32). Block = (b, head, 64-query tile); 256 threads.
// q,k,v are [dh=64, N] slices of g_qkv (channel-major). scale folded into Q.
// Online softmax; O accumulated 4x4 per thread (rows i, cols d).
// Dynamic smem: Qs[64][64] Ks[64][64] Vs[64][65] Ps[64][68] = 66816 B.
// ---------------------------------------------------------------------------
__global__ void attn_kernel() {
    extern __shared__ float sm[];
    float* Qs = sm;                 // [64][64]
    float* Ks = Qs + 64 * 64;       // [64][64]
    float* Vs = Ks + 64 * 64;       // [64][65]
    float* Ps = Vs + 64 * 65;       // [64][68]

    int b = blockIdx.z, hh = blockIdx.y;
    int qbase = blockIdx.x << 6;
    const float* qp = g_qkv + ((size_t)b * 768 + hh * DH_) * N_;
    const float* kp = qp + (size_t)256 * N_;
    const float* vp = qp + (size_t)512 * N_;

    int tid = threadIdx.x, ty = tid >> 4, tx = tid & 15;

    // Load Q tile (scaled by 1/sqrt(dh) = 0.125)
#pragma unroll
    for (int r = 0; r < 4; r++) {
        int d = (tid >> 4) + r * 16;
        int i4 = (tid & 15) << 2;
        float4 v = *(const float4*)(qp + (size_t)d * N_ + qbase + i4);
        v.x *= 0.125f; v.y *= 0.125f; v.z *= 0.125f; v.w *= 0.125f;
        *(float4*)&Qs[d * 64 + i4] = v;
    }

    float m[4], l[4], O[4][4];
#pragma unroll
    for (int ii = 0; ii < 4; ii++) {
        m[ii] = -1e30f; l[ii] = 0.f;
#pragma unroll
        for (int dd = 0; dd < 4; dd++) O[ii][dd] = 0.f;
    }

    for (int kt = 0; kt < N_; kt += 64) {
        __syncthreads();  // protect Ks/Vs/Qs from prior phase
        // Load K, V tiles
#pragma unroll
        for (int r = 0; r < 4; r++) {
            int d = (tid >> 4) + r * 16;
            int i4 = (tid & 15) << 2;
            *(float4*)&Ks[d * 64 + i4] =
                *(const float4*)(kp + (size_t)d * N_ + kt + i4);
            float4 vv = *(const float4*)(vp + (size_t)d * N_ + kt + i4);
            Vs[d * 65 + i4 + 0] = vv.x; Vs[d * 65 + i4 + 1] = vv.y;
            Vs[d * 65 + i4 + 2] = vv.z; Vs[d * 65 + i4 + 3] = vv.w;
        }
        __syncthreads();

        // S = Q^T K  (rows i = ty*4.., cols j = tx*4..)
        float acc[4][4] = {};
#pragma unroll
        for (int d = 0; d < 64; d++) {
            float4 a = *(float4*)&Qs[d * 64 + (ty << 2)];
            float4 kk = *(float4*)&Ks[d * 64 + (tx << 2)];
            float av[4] = {a.x, a.y, a.z, a.w};
            float bv[4] = {kk.x, kk.y, kk.z, kk.w};
#pragma unroll
            for (int ii = 0; ii < 4; ii++)
#pragma unroll
                for (int jj = 0; jj < 4; jj++) acc[ii][jj] += av[ii] * bv[jj];
        }

        // Online softmax (row reductions across the 16-lane tx group)
#pragma unroll
        for (int ii = 0; ii < 4; ii++) {
            float tm = fmaxf(fmaxf(acc[ii][0], acc[ii][1]),
                             fmaxf(acc[ii][2], acc[ii][3]));
            tm = fmaxf(tm, __shfl_xor_sync(0xffffffffu, tm, 8));
            tm = fmaxf(tm, __shfl_xor_sync(0xffffffffu, tm, 4));
            tm = fmaxf(tm, __shfl_xor_sync(0xffffffffu, tm, 2));
            tm = fmaxf(tm, __shfl_xor_sync(0xffffffffu, tm, 1));
            float mn = fmaxf(m[ii], tm);
            float f = __expf(m[ii] - mn);
            float rs = 0.f;
#pragma unroll
            for (int jj = 0; jj < 4; jj++) {
                float p = __expf(acc[ii][jj] - mn);
                acc[ii][jj] = p;
                rs += p;
            }
            rs += __shfl_xor_sync(0xffffffffu, rs, 8);
            rs += __shfl_xor_sync(0xffffffffu, rs, 4);
            rs += __shfl_xor_sync(0xffffffffu, rs, 2);
            rs += __shfl_xor_sync(0xffffffffu, rs, 1);
            l[ii] = l[ii] * f + rs;
            m[ii] = mn;
#pragma unroll
            for (int dd = 0; dd < 4; dd++) O[ii][dd] *= f;
            *(float4*)&Ps[(ty * 4 + ii) * 68 + (tx << 2)] =
                make_float4(acc[ii][0], acc[ii][1], acc[ii][2], acc[ii][3]);
        }
        __syncthreads();

        // O += P * V^T  (O rows i = ty*4.., cols d = tx*4..)
#pragma unroll 4
        for (int j = 0; j < 64; j++) {
            float pv[4], vv[4];
#pragma unroll
            for (int ii = 0; ii < 4; ii++) pv[ii] = Ps[(ty * 4 + ii) * 68 + j];
#pragma unroll
            for (int dd = 0; dd < 4; dd++) vv[dd] = Vs[(tx * 4 + dd) * 65 + j];
#pragma unroll
            for (int ii = 0; ii < 4; ii++)
#pragma unroll
                for (int dd = 0; dd < 4; dd++) O[ii][dd] += pv[ii] * vv[dd];
        }
    }

    // Epilogue: normalize and write [B, C, N] channel-major
#pragma unroll
    for (int ii = 0; ii < 4; ii++) {
        float inv = 1.0f / l[ii];
#pragma unroll
        for (int dd = 0; dd < 4; dd++) {
            int c = hh * DH_ + tx * 4 + dd;
            g_ao[((size_t)b * C_ + c) * N_ + qbase + ty * 4 + ii] =
                O[ii][dd] * inv;
        }
    }
}

// ---------------------------------------------------------------------------
extern "C" void kernel_launch(void* const* d_in, const int* in_sizes, int n_in,
                              void* d_out, int out_size) {
    const float* x      = (const float*)d_in[0];
    const float* gn_w   = (const float*)d_in[1];
    const float* gn_b   = (const float*)d_in[2];
    const float* w_qkv  = (const float*)d_in[3];
    const float* b_qkv  = (const float*)d_in[4];
    const float* w_proj = (const float*)d_in[5];
    const float* b_proj = (const float*)d_in[6];
    float* out = (float*)d_out;

    static const int ATTN_SMEM = (64 * 64 + 64 * 64 + 64 * 65 + 64 * 68) * 4;
    cudaFuncSetAttribute(attn_kernel,
                         cudaFuncAttributeMaxDynamicSharedMemorySize, ATTN_SMEM);

    gn_kernel<<<B_ * G_, 256>>>(x, gn_w, gn_b);
    qkv_gemm_kernel<<<dim3(N_ / 64, 768 / 64, B_), 256>>>(w_qkv, b_qkv);
    attn_kernel<<<dim3(N_ / 64, NH_, B_), 256, ATTN_SMEM>>>();
    proj_gemm_kernel<<<dim3(N_ / 64, C_ / 64, B_), 256>>>(w_proj, b_proj, x, out);
}

// round 2
// speedup vs baseline: 1.8209x; 1.8209x over previous
#include <cuda_runtime.h>
#include <cuda_bf16.h>
#include <cstdint>

#define B_ 4
#define C_ 256
#define N_ 4096
#define NH_ 4
#define DH_ 64
#define CPG_ 32

// Scratch
__device__ float g_h[B_ * C_ * N_];
__device__ float g_qkv[B_ * 3 * C_ * N_];
__device__ float g_ao[B_ * C_ * N_];

__device__ __forceinline__ float f2tf(float x) {
    uint32_t u;
    asm("cvt.rna.tf32.f32 %0, %1;" : "=r"(u) : "f"(x));
    return __uint_as_float(u);
}

__device__ __forceinline__ void mma_tf32(float* d, const uint32_t* a,
                                         const uint32_t* b) {
    asm volatile(
        "mma.sync.aligned.m16n8k8.row.col.f32.tf32.tf32.f32 "
        "{%0,%1,%2,%3}, {%4,%5,%6,%7}, {%8,%9}, {%0,%1,%2,%3};"
        : "+f"(d[0]), "+f"(d[1]), "+f"(d[2]), "+f"(d[3])
        : "r"(a[0]), "r"(a[1]), "r"(a[2]), "r"(a[3]), "r"(b[0]), "r"(b[1]));
}

// ---------------------------------------------------------------------------
// GroupNorm (unchanged)
// ---------------------------------------------------------------------------
__global__ void gn_kernel(const float* __restrict__ x,
                          const float* __restrict__ gn_w,
                          const float* __restrict__ gn_b) {
    const int total = CPG_ * N_;
    int b = blockIdx.x >> 3, g = blockIdx.x & 7;
    const float* xp = x + (size_t)(b * C_ + g * CPG_) * N_;
    float* hp = g_h + (size_t)(b * C_ + g * CPG_) * N_;

    float s = 0.f, ss = 0.f;
    for (int i = threadIdx.x * 4; i < total; i += blockDim.x * 4) {
        float4 v = *(const float4*)(xp + i);
        s += v.x + v.y + v.z + v.w;
        ss += v.x * v.x + v.y * v.y + v.z * v.z + v.w * v.w;
    }
#pragma unroll
    for (int o = 16; o; o >>= 1) {
        s += __shfl_xor_sync(0xffffffffu, s, o);
        ss += __shfl_xor_sync(0xffffffffu, ss, o);
    }
    __shared__ float rs[8], rss[8];
    __shared__ float s_mu, s_rstd;
    int wid = threadIdx.x >> 5, lid = threadIdx.x & 31;
    if (lid == 0) { rs[wid] = s; rss[wid] = ss; }
    __syncthreads();
    if (threadIdx.x == 0) {
        float S = 0.f, SS = 0.f;
#pragma unroll
        for (int w = 0; w < 8; w++) { S += rs[w]; SS += rss[w]; }
        float mu = S / (float)total;
        float var = SS / (float)total - mu * mu;
        s_mu = mu;
        s_rstd = rsqrtf(var + 1e-5f);
    }
    __syncthreads();
    float mu = s_mu, rstd = s_rstd;
    for (int i = threadIdx.x * 4; i < total; i += blockDim.x * 4) {
        int c = g * CPG_ + (i >> 12);
        float w = gn_w[c] * rstd;
        float bb = gn_b[c] - mu * w;
        float4 v = *(const float4*)(xp + i);
        v.x = v.x * w + bb; v.y = v.y * w + bb;
        v.z = v.z * w + bb; v.w = v.w * w + bb;
        *(float4*)(hp + i) = v;
    }
}

// ---------------------------------------------------------------------------
// QKV GEMM (unchanged, fp32 SIMT)
// ---------------------------------------------------------------------------
__global__ void qkv_gemm_kernel(const float* __restrict__ W,
                                const float* __restrict__ bias) {
    __shared__ float Ast[16][68];
    __shared__ float Bs[16][64];
    int b = blockIdx.z;
    int ot = blockIdx.y << 6, nt = blockIdx.x << 6;
    int tid = threadIdx.x, ty = tid >> 4, tx = tid & 15;
    const float* Hb = g_h + (size_t)b * C_ * N_;
    float acc[4][4] = {};

    for (int k0 = 0; k0 < C_; k0 += 16) {
        {
            int o = tid >> 2, c4 = (tid & 3) << 2;
            float4 w4 = *(const float4*)(W + (size_t)(ot + o) * C_ + k0 + c4);
            Ast[c4 + 0][o] = w4.x; Ast[c4 + 1][o] = w4.y;
            Ast[c4 + 2][o] = w4.z; Ast[c4 + 3][o] = w4.w;
        }
        {
            int cc = tid >> 4, n4 = (tid & 15) << 2;
            *(float4*)&Bs[cc][n4] =
                *(const float4*)(Hb + (size_t)(k0 + cc) * N_ + nt + n4);
        }
        __syncthreads();
#pragma unroll
        for (int kc = 0; kc < 16; kc++) {
            float4 a = *(float4*)&Ast[kc][ty << 2];
            float4 bv4 = *(float4*)&Bs[kc][tx << 2];
            float av[4] = {a.x, a.y, a.z, a.w};
            float bv[4] = {bv4.x, bv4.y, bv4.z, bv4.w};
#pragma unroll
            for (int ii = 0; ii < 4; ii++)
#pragma unroll
                for (int jj = 0; jj < 4; jj++) acc[ii][jj] += av[ii] * bv[jj];
        }
        __syncthreads();
    }
#pragma unroll
    for (int ii = 0; ii < 4; ii++) {
        int o = ot + (ty << 2) + ii;
        float bo = bias[o];
        float4 r = make_float4(acc[ii][0] + bo, acc[ii][1] + bo,
                               acc[ii][2] + bo, acc[ii][3] + bo);
        *(float4*)(g_qkv + ((size_t)b * 768 + o) * N_ + nt + (tx << 2)) = r;
    }
}

// ---------------------------------------------------------------------------
// Proj GEMM + residual (unchanged)
// ---------------------------------------------------------------------------
__global__ void proj_gemm_kernel(const float* __restrict__ W,
                                 const float* __restrict__ bias,
                                 const float* __restrict__ x,
                                 float* __restrict__ out) {
    __shared__ float Ast[16][68];
    __shared__ float Bs[16][64];
    int b = blockIdx.z;
    int ot = blockIdx.y << 6, nt = blockIdx.x << 6;
    int tid = threadIdx.x, ty = tid >> 4, tx = tid & 15;
    const float* Hb = g_ao + (size_t)b * C_ * N_;
    float acc[4][4] = {};

    for (int k0 = 0; k0 < C_; k0 += 16) {
        {
            int o = tid >> 2, c4 = (tid & 3) << 2;
            float4 w4 = *(const float4*)(W + (size_t)(ot + o) * C_ + k0 + c4);
            Ast[c4 + 0][o] = w4.x; Ast[c4 + 1][o] = w4.y;
            Ast[c4 + 2][o] = w4.z; Ast[c4 + 3][o] = w4.w;
        }
        {
            int cc = tid >> 4, n4 = (tid & 15) << 2;
            *(float4*)&Bs[cc][n4] =
                *(const float4*)(Hb + (size_t)(k0 + cc) * N_ + nt + n4);
        }
        __syncthreads();
#pragma unroll
        for (int kc = 0; kc < 16; kc++) {
            float4 a = *(float4*)&Ast[kc][ty << 2];
            float4 bv4 = *(float4*)&Bs[kc][tx << 2];
            float av[4] = {a.x, a.y, a.z, a.w};
            float bv[4] = {bv4.x, bv4.y, bv4.z, bv4.w};
#pragma unroll
            for (int ii = 0; ii < 4; ii++)
#pragma unroll
                for (int jj = 0; jj < 4; jj++) acc[ii][jj] += av[ii] * bv[jj];
        }
        __syncthreads();
    }
#pragma unroll
    for (int ii = 0; ii < 4; ii++) {
        int o = ot + (ty << 2) + ii;
        float bo = bias[o];
        size_t idx = ((size_t)b * C_ + o) * N_ + nt + (tx << 2);
        float4 xr = *(const float4*)(x + idx);
        float4 r = make_float4(acc[ii][0] + bo + xr.x, acc[ii][1] + bo + xr.y,
                               acc[ii][2] + bo + xr.z, acc[ii][3] + bo + xr.w);
        *(float4*)(out + idx) = r;
    }
}

// ---------------------------------------------------------------------------
// Flash attention, tf32 tensor cores.
// Block: (b, h, 128-query tile). 4 warps; warp w owns query rows w*32..w*32+31
// (two m16 fragments). K/V streamed in 64-key tiles.
// Smem strides: Qs/Vs/Ps 68 (conflict-free A / V-B frag loads), Ks 72.
// ---------------------------------------------------------------------------
#define QS_STR 68
#define KS_STR 72
#define VS_STR 68
#define PS_STR 68

__global__ void __launch_bounds__(128) attn_kernel() {
    extern __shared__ float sm[];
    float* Qs = sm;                        // [128][68]
    float* Ks = Qs + 128 * QS_STR;         // [64][72]
    float* Vs = Ks + 64 * KS_STR;          // [64][68]
    float* Ps = Vs + 64 * VS_STR;          // 4 x [32][68]

    int b = blockIdx.z, hh = blockIdx.y;
    int qbase = blockIdx.x << 7;           // *128
    const float* qp = g_qkv + ((size_t)b * 768 + hh * DH_) * N_;
    const float* kp = qp + (size_t)256 * N_;
    const float* vp = qp + (size_t)512 * N_;

    int tid = threadIdx.x;
    int warp = tid >> 5, lane = tid & 31;
    int lg = lane >> 2, lq = lane & 3;     // group row, quad col
    float* Pw = Ps + warp * 32 * PS_STR;

    // ---- Load Q (transpose [d][i] -> Qs[i][d]), scale 0.125, tf32 round ----
    {
        int d = tid >> 1;
        int ih = (tid & 1) << 6;           // 0 or 64
        const float* qr = qp + (size_t)d * N_ + qbase + ih;
#pragma unroll
        for (int k = 0; k < 64; k += 4) {
            float4 v = *(const float4*)(qr + k);
            Qs[(ih + k + 0) * QS_STR + d] = f2tf(v.x * 0.125f);
            Qs[(ih + k + 1) * QS_STR + d] = f2tf(v.y * 0.125f);
            Qs[(ih + k + 2) * QS_STR + d] = f2tf(v.z * 0.125f);
            Qs[(ih + k + 3) * QS_STR + d] = f2tf(v.w * 0.125f);
        }
    }

    float Oacc[2][8][4];
    float mrow[4], lrow[4];
#pragma unroll
    for (int mt = 0; mt < 2; mt++)
#pragma unroll
        for (int nt = 0; nt < 8; nt++)
#pragma unroll
            for (int c = 0; c < 4; c++) Oacc[mt][nt][c] = 0.f;
#pragma unroll
    for (int s = 0; s < 4; s++) { mrow[s] = -1e30f; lrow[s] = 0.f; }

    for (int kt = 0; kt < N_; kt += 64) {
        __syncthreads();
        // ---- Load K, V tiles ([d][j], tf32) ----
        {
            int d = tid >> 1;
            int jh = (tid & 1) << 5;       // 0 or 32
            const float* kr = kp + (size_t)d * N_ + kt + jh;
            const float* vr = vp + (size_t)d * N_ + kt + jh;
#pragma unroll
            for (int k = 0; k < 32; k += 4) {
                float4 kv = *(const float4*)(kr + k);
                float4 vv = *(const float4*)(vr + k);
                float* ksd = Ks + d * KS_STR + jh + k;
                ksd[0] = f2tf(kv.x); ksd[1] = f2tf(kv.y);
                ksd[2] = f2tf(kv.z); ksd[3] = f2tf(kv.w);
                float* vsd = Vs + d * VS_STR + jh + k;
                vsd[0] = f2tf(vv.x); vsd[1] = f2tf(vv.y);
                vsd[2] = f2tf(vv.z); vsd[3] = f2tf(vv.w);
            }
        }
        __syncthreads();

        // ---- S = Q K  (per warp: 32 x 64) ----
        float Sacc[2][8][4];
#pragma unroll
        for (int mt = 0; mt < 2; mt++)
#pragma unroll
            for (int nt = 0; nt < 8; nt++)
#pragma unroll
                for (int c = 0; c < 4; c++) Sacc[mt][nt][c] = 0.f;

#pragma unroll
        for (int kk = 0; kk < 8; kk++) {
            uint32_t A[2][4];
            int cb = kk * 8 + lq;
#pragma unroll
            for (int mt = 0; mt < 2; mt++) {
                int r = warp * 32 + mt * 16 + lg;
                A[mt][0] = __float_as_uint(Qs[r * QS_STR + cb]);
                A[mt][1] = __float_as_uint(Qs[(r + 8) * QS_STR + cb]);
                A[mt][2] = __float_as_uint(Qs[r * QS_STR + cb + 4]);
                A[mt][3] = __float_as_uint(Qs[(r + 8) * QS_STR + cb + 4]);
            }
#pragma unroll
            for (int nt = 0; nt < 8; nt++) {
                uint32_t Bf[2];
                int dr = kk * 8 + lq;
                int jc = nt * 8 + lg;
                Bf[0] = __float_as_uint(Ks[dr * KS_STR + jc]);
                Bf[1] = __float_as_uint(Ks[(dr + 4) * KS_STR + jc]);
                mma_tf32(Sacc[0][nt], A[0], Bf);
                mma_tf32(Sacc[1][nt], A[1], Bf);
            }
        }

        // ---- Online softmax; store P (tf32) into warp-private smem ----
#pragma unroll
        for (int mt = 0; mt < 2; mt++) {
#pragma unroll
            for (int hi = 0; hi < 2; hi++) {
                int s = mt * 2 + hi;
                float rowmax = -1e30f;
#pragma unroll
                for (int nt = 0; nt < 8; nt++)
                    rowmax = fmaxf(rowmax, fmaxf(Sacc[mt][nt][hi * 2],
                                                 Sacc[mt][nt][hi * 2 + 1]));
                rowmax = fmaxf(rowmax, __shfl_xor_sync(0xffffffffu, rowmax, 1));
                rowmax = fmaxf(rowmax, __shfl_xor_sync(0xffffffffu, rowmax, 2));
                float mnew = fmaxf(mrow[s], rowmax);
                float f = __expf(mrow[s] - mnew);
                float sum = 0.f;
                int il = mt * 16 + lg + hi * 8;
#pragma unroll
                for (int nt = 0; nt < 8; nt++) {
#pragma unroll
                    for (int c = 0; c < 2; c++) {
                        float p = f2tf(__expf(Sacc[mt][nt][hi * 2 + c] - mnew));
                        sum += p;
                        Pw[il * PS_STR + nt * 8 + 2 * lq + c] = p;
                        Oacc[mt][nt][hi * 2 + c] *= f;
                    }
                }
                sum += __shfl_xor_sync(0xffffffffu, sum, 1);
                sum += __shfl_xor_sync(0xffffffffu, sum, 2);
                lrow[s] = lrow[s] * f + sum;
                mrow[s] = mnew;
            }
        }
        __syncwarp();

        // ---- O += P V   (K dim = keys j) ----
#pragma unroll
        for (int kk = 0; kk < 8; kk++) {
            uint32_t A[2][4];
            int cb = kk * 8 + lq;
#pragma unroll
            for (int mt = 0; mt < 2; mt++) {
                int r = mt * 16 + lg;
                A[mt][0] = __float_as_uint(Pw[r * PS_STR + cb]);
                A[mt][1] = __float_as_uint(Pw[(r + 8) * PS_STR + cb]);
                A[mt][2] = __float_as_uint(Pw[r * PS_STR + cb + 4]);
                A[mt][3] = __float_as_uint(Pw[(r + 8) * PS_STR + cb + 4]);
            }
#pragma unroll
            for (int nt = 0; nt < 8; nt++) {
                uint32_t Bf[2];
                int jr = kk * 8 + lq;          // j (K-dim)
                int dc = nt * 8 + lg;          // d (N-dim)
                Bf[0] = __float_as_uint(Vs[dc * VS_STR + jr]);
                Bf[1] = __float_as_uint(Vs[dc * VS_STR + jr + 4]);
                mma_tf32(Oacc[0][nt], A[0], Bf);
                mma_tf32(Oacc[1][nt], A[1], Bf);
            }
        }
        __syncwarp();  // Pw reuse safety next iter (within-warp anyway)
    }

    // ---- Epilogue: normalize, stage into Qs, coalesced store ----
    __syncthreads();
#pragma unroll
    for (int mt = 0; mt < 2; mt++) {
#pragma unroll
        for (int hi = 0; hi < 2; hi++) {
            float inv = 1.0f / lrow[mt * 2 + hi];
            int r = warp * 32 + mt * 16 + lg + hi * 8;
#pragma unroll
            for (int nt = 0; nt < 8; nt++) {
                Qs[r * QS_STR + nt * 8 + 2 * lq + 0] =
                    Oacc[mt][nt][hi * 2 + 0] * inv;
                Qs[r * QS_STR + nt * 8 + 2 * lq + 1] =
                    Oacc[mt][nt][hi * 2 + 1] * inv;
            }
        }
    }
    __syncthreads();
    {
        int d = tid >> 1;
        int ih = (tid & 1) << 6;
        float* op = g_ao + ((size_t)b * C_ + hh * DH_ + d) * N_ + qbase + ih;
#pragma unroll
        for (int k = 0; k < 64; k += 4) {
            float4 v = make_float4(Qs[(ih + k + 0) * QS_STR + d],
                                   Qs[(ih + k + 1) * QS_STR + d],
                                   Qs[(ih + k + 2) * QS_STR + d],
                                   Qs[(ih + k + 3) * QS_STR + d]);
            *(float4*)(op + k) = v;
        }
    }
}

// ---------------------------------------------------------------------------
extern "C" void kernel_launch(void* const* d_in, const int* in_sizes, int n_in,
                              void* d_out, int out_size) {
    const float* x      = (const float*)d_in[0];
    const float* gn_w   = (const float*)d_in[1];
    const float* gn_b   = (const float*)d_in[2];
    const float* w_qkv  = (const float*)d_in[3];
    const float* b_qkv  = (const float*)d_in[4];
    const float* w_proj = (const float*)d_in[5];
    const float* b_proj = (const float*)d_in[6];
    float* out = (float*)d_out;

    static const int ATTN_SMEM =
        (128 * QS_STR + 64 * KS_STR + 64 * VS_STR + 4 * 32 * PS_STR) * 4;
    cudaFuncSetAttribute(attn_kernel,
                         cudaFuncAttributeMaxDynamicSharedMemorySize, ATTN_SMEM);

    gn_kernel<<<B_ * 8, 256>>>(x, gn_w, gn_b);
    qkv_gemm_kernel<<<dim3(N_ / 64, 768 / 64, B_), 256>>>(w_qkv, b_qkv);
    attn_kernel<<<dim3(N_ / 128, NH_, B_), 128, ATTN_SMEM>>>();
    proj_gemm_kernel<<<dim3(N_ / 64, C_ / 64, B_), 256>>>(w_proj, b_proj, x, out);
}

// round 5
// speedup vs baseline: 4.2243x; 2.3199x over previous
#include <cuda_runtime.h>
#include <cuda_fp16.h>
#include <cstdint>

#define B_ 4
#define C_ 256
#define N_ 4096
#define NH_ 4
#define DH_ 64
#define CPG_ 32

// Scratch (device globals — only ever referenced from DEVICE code)
__device__ float g_h[B_ * C_ * N_];         // groupnorm out (fp32)
__device__ __half g_qkvh[B_ * 3 * C_ * N_]; // qkv out (fp16)
__device__ float g_ao[B_ * C_ * N_];        // attention out (fp32)

// ---------------------------------------------------------------------------
// helpers
// ---------------------------------------------------------------------------
__device__ __forceinline__ float f2tf(float x) {
    uint32_t u;
    asm("cvt.rna.tf32.f32 %0, %1;" : "=r"(u) : "f"(x));
    return __uint_as_float(u);
}
__device__ __forceinline__ float ex2f(float x) {
    float y;
    asm("ex2.approx.ftz.f32 %0, %1;" : "=f"(y) : "f"(x));
    return y;
}
__device__ __forceinline__ void mma_tf32(float* d, const uint32_t* a,
                                         const uint32_t* b) {
    asm volatile(
        "mma.sync.aligned.m16n8k8.row.col.f32.tf32.tf32.f32 "
        "{%0,%1,%2,%3}, {%4,%5,%6,%7}, {%8,%9}, {%0,%1,%2,%3};"
        : "+f"(d[0]), "+f"(d[1]), "+f"(d[2]), "+f"(d[3])
        : "r"(a[0]), "r"(a[1]), "r"(a[2]), "r"(a[3]), "r"(b[0]), "r"(b[1]));
}
__device__ __forceinline__ void mma_f16(float* d, const uint32_t* a,
                                        const uint32_t* b) {
    asm volatile(
        "mma.sync.aligned.m16n8k16.row.col.f32.f16.f16.f32 "
        "{%0,%1,%2,%3}, {%4,%5,%6,%7}, {%8,%9}, {%0,%1,%2,%3};"
        : "+f"(d[0]), "+f"(d[1]), "+f"(d[2]), "+f"(d[3])
        : "r"(a[0]), "r"(a[1]), "r"(a[2]), "r"(a[3]), "r"(b[0]), "r"(b[1]));
}
__device__ __forceinline__ void ldsm_x4(uint32_t* r, const void* p) {
    uint32_t a = (uint32_t)__cvta_generic_to_shared(p);
    asm volatile(
        "ldmatrix.sync.aligned.m8n8.x4.shared.b16 {%0,%1,%2,%3}, [%4];"
        : "=r"(r[0]), "=r"(r[1]), "=r"(r[2]), "=r"(r[3]) : "r"(a));
}
__device__ __forceinline__ void ldsm_x4_t(uint32_t* r, const void* p) {
    uint32_t a = (uint32_t)__cvta_generic_to_shared(p);
    asm volatile(
        "ldmatrix.sync.aligned.m8n8.x4.trans.shared.b16 {%0,%1,%2,%3}, [%4];"
        : "=r"(r[0]), "=r"(r[1]), "=r"(r[2]), "=r"(r[3]) : "r"(a));
}

// ---------------------------------------------------------------------------
// GroupNorm
// ---------------------------------------------------------------------------
__global__ void gn_kernel(const float* __restrict__ x,
                          const float* __restrict__ gn_w,
                          const float* __restrict__ gn_b) {
    const int total = CPG_ * N_;
    int b = blockIdx.x >> 3, g = blockIdx.x & 7;
    const float* xp = x + (size_t)(b * C_ + g * CPG_) * N_;
    float* hp = g_h + (size_t)(b * C_ + g * CPG_) * N_;

    float s = 0.f, ss = 0.f;
    for (int i = threadIdx.x * 4; i < total; i += blockDim.x * 4) {
        float4 v = *(const float4*)(xp + i);
        s += v.x + v.y + v.z + v.w;
        ss += v.x * v.x + v.y * v.y + v.z * v.z + v.w * v.w;
    }
#pragma unroll
    for (int o = 16; o; o >>= 1) {
        s += __shfl_xor_sync(0xffffffffu, s, o);
        ss += __shfl_xor_sync(0xffffffffu, ss, o);
    }
    __shared__ float rs[8], rss[8];
    __shared__ float s_mu, s_rstd;
    int wid = threadIdx.x >> 5, lid = threadIdx.x & 31;
    if (lid == 0) { rs[wid] = s; rss[wid] = ss; }
    __syncthreads();
    if (threadIdx.x == 0) {
        float S = 0.f, SS = 0.f;
#pragma unroll
        for (int w = 0; w < 8; w++) { S += rs[w]; SS += rss[w]; }
        float mu = S / (float)total;
        float var = SS / (float)total - mu * mu;
        s_mu = mu;
        s_rstd = rsqrtf(var + 1e-5f);
    }
    __syncthreads();
    float mu = s_mu, rstd = s_rstd;
    for (int i = threadIdx.x * 4; i < total; i += blockDim.x * 4) {
        int c = g * CPG_ + (i >> 12);
        float w = gn_w[c] * rstd;
        float bb = gn_b[c] - mu * w;
        float4 v = *(const float4*)(xp + i);
        v.x = v.x * w + bb; v.y = v.y * w + bb;
        v.z = v.z * w + bb; v.w = v.w * w + bb;
        *(float4*)(hp + i) = v;
    }
}

// ---------------------------------------------------------------------------
// tf32 tensor-core GEMM: C[o][n] = sum_c W[o][c] * H[c][n] (+bias)(+res)
// Block 128x128, k-chunks of 32, 256 threads = 8 warps (4 x 2), warp 32x64.
// MODE 0: H = g_h (device symbol), out = fp16 g_qkvh.
// MODE 1: H = g_ao (device symbol), out = fp32 outf + bias + residual.
// Scratch accessed ONLY via device symbols (never passed from host).
// ---------------------------------------------------------------------------
#define GS 132
template <int MODE>
__global__ void __launch_bounds__(256) gemm_kernel(
    const float* __restrict__ W, const float* __restrict__ bias,
    const float* __restrict__ xres, float* __restrict__ outf) {
    __shared__ float As[32][GS];  // [c][o]
    __shared__ float Bs[32][GS];  // [c][n]
    int b = blockIdx.z;
    int ot = blockIdx.y << 7, nt0 = blockIdx.x << 7;
    int tid = threadIdx.x;
    int warp = tid >> 5, lane = tid & 31, lg = lane >> 2, lq = lane & 3;
    int Mb = (warp >> 1) << 5, Nb = (warp & 1) << 6;
    const float* Hb = (MODE == 0 ? g_h : g_ao) + (size_t)b * C_ * N_;

    float acc[2][8][4] = {};

    for (int k0 = 0; k0 < C_; k0 += 32) {
        __syncthreads();
        {   // W tile: 128 o x 32 c -> As[c][o] (tf32)
            int o = tid >> 1, part = tid & 1;
            const float4* src =
                (const float4*)(W + (size_t)(ot + o) * C_ + k0 + part * 16);
#pragma unroll
            for (int j = 0; j < 4; j++) {
                float4 v = src[j];
                int c = part * 16 + j * 4;
                As[c + 0][o] = f2tf(v.x); As[c + 1][o] = f2tf(v.y);
                As[c + 2][o] = f2tf(v.z); As[c + 3][o] = f2tf(v.w);
            }
        }
        {   // H tile: 32 c x 128 n -> Bs[c][n] (tf32)
            int c = tid >> 3, np = (tid & 7) << 4;
            const float4* src =
                (const float4*)(Hb + (size_t)(k0 + c) * N_ + nt0 + np);
#pragma unroll
            for (int j = 0; j < 4; j++) {
                float4 v = src[j];
                v.x = f2tf(v.x); v.y = f2tf(v.y);
                v.z = f2tf(v.z); v.w = f2tf(v.w);
                *(float4*)&Bs[c][np + j * 4] = v;
            }
        }
        __syncthreads();
#pragma unroll
        for (int kk = 0; kk < 4; kk++) {
            int kb = kk << 3;
            uint32_t A[2][4];
#pragma unroll
            for (int mt = 0; mt < 2; mt++) {
                int m = Mb + mt * 16 + lg;
                A[mt][0] = __float_as_uint(As[kb + lq][m]);
                A[mt][1] = __float_as_uint(As[kb + lq][m + 8]);
                A[mt][2] = __float_as_uint(As[kb + lq + 4][m]);
                A[mt][3] = __float_as_uint(As[kb + lq + 4][m + 8]);
            }
#pragma unroll
            for (int nt = 0; nt < 8; nt++) {
                uint32_t Bf[2];
                int n = Nb + nt * 8 + lg;
                Bf[0] = __float_as_uint(Bs[kb + lq][n]);
                Bf[1] = __float_as_uint(Bs[kb + lq + 4][n]);
                mma_tf32(acc[0][nt], A[0], Bf);
                mma_tf32(acc[1][nt], A[1], Bf);
            }
        }
    }

    // Epilogue
#pragma unroll
    for (int mt = 0; mt < 2; mt++) {
#pragma unroll
        for (int hi = 0; hi < 2; hi++) {
            int o = ot + Mb + mt * 16 + lg + hi * 8;
            float bo = bias[o];
#pragma unroll
            for (int nt = 0; nt < 8; nt++) {
                int n = nt0 + Nb + nt * 8 + 2 * lq;
                float v0 = acc[mt][nt][hi * 2 + 0] + bo;
                float v1 = acc[mt][nt][hi * 2 + 1] + bo;
                if (MODE == 0) {
                    __half2 h2;
                    h2.x = __float2half_rn(v0);
                    h2.y = __float2half_rn(v1);
                    *(__half2*)(g_qkvh + ((size_t)b * 768 + o) * N_ + n) = h2;
                } else {
                    size_t idx = ((size_t)b * C_ + o) * N_ + n;
                    float2 xr = *(const float2*)(xres + idx);
                    *(float2*)(outf + idx) = make_float2(v0 + xr.x, v1 + xr.y);
                }
            }
        }
    }
}

// ---------------------------------------------------------------------------
// Flash attention, fp16 mma.m16n8k16 + ldmatrix.
// Block: (b, h, 128-q tile), 4 warps x 32 rows. K-tiles of 64.
// Smem (fp16): Qs[64 d][136 i]  Ks[64 d][72 j]  Vs[64 d][72 j]  Pw 4x[32 i][72 j]
// ---------------------------------------------------------------------------
#define QSTR 136
#define KSTR 72
#define VSTR 72
#define PSTR 72
#define ATTN_SMEM ((64 * QSTR + 64 * KSTR + 64 * VSTR + 4 * 32 * PSTR) * 2)

__global__ void __launch_bounds__(128, 3) attn_kernel() {
    extern __shared__ __half smb[];
    __half* Qs = smb;
    __half* Ks = Qs + 64 * QSTR;
    __half* Vs = Ks + 64 * KSTR;
    __half* Ps = Vs + 64 * VSTR;

    int b = blockIdx.z, hh = blockIdx.y;
    int qbase = blockIdx.x << 7;
    const __half* qp = g_qkvh + ((size_t)b * 768 + hh * DH_) * N_;
    const __half* kp = qp + (size_t)256 * N_;
    const __half* vp = qp + (size_t)512 * N_;

    int tid = threadIdx.x;
    int warp = tid >> 5, lane = tid & 31, lg = lane >> 2, lq = lane & 3;
    __half* Pw = Ps + warp * 32 * PSTR;

    // Fragment base offsets
    int arow = (lane & 7) | ((lane & 16) >> 1);
    int acol = lane & 8;
    const __half* qA = Qs + arow * QSTR + warp * 32 + acol;
    int brow = lane & 15;
    int bcol = (lane & 16) >> 1;
    const __half* kB = Ks + brow * KSTR + bcol;
    int vrow = (lane & 7) | ((lane & 16) >> 1);
    int vcol = lane & 8;
    const __half* vB = Vs + vrow * VSTR + vcol;
    const __half* pA = Pw + (lane & 15) * PSTR + ((lane >> 4) << 3);

    // Load Q tile (pure fp16 copy, [d][i])
    {
        int d = tid >> 1, ih = (tid & 1) << 6;
        const uint4* src = (const uint4*)(qp + (size_t)d * N_ + qbase + ih);
        uint4* dst = (uint4*)(Qs + d * QSTR + ih);
#pragma unroll
        for (int k = 0; k < 8; k++) dst[k] = src[k];
    }

    float Oacc[2][8][4] = {};
    float mrow[4], lrow[4];
#pragma unroll
    for (int s = 0; s < 4; s++) { mrow[s] = -1e30f; lrow[s] = 0.f; }
    const float SC = 0.125f * 1.4426950408889634f;  // 1/sqrt(dh) * log2(e)

    for (int kt = 0; kt < N_; kt += 64) {
        __syncthreads();
        {   // K/V tile copy (fp16)
            int d = tid >> 1, jh = (tid & 1) << 5;
            const uint4* ks = (const uint4*)(kp + (size_t)d * N_ + kt + jh);
            const uint4* vs = (const uint4*)(vp + (size_t)d * N_ + kt + jh);
            uint4* kd = (uint4*)(Ks + d * KSTR + jh);
            uint4* vd = (uint4*)(Vs + d * VSTR + jh);
#pragma unroll
            for (int k = 0; k < 4; k++) { kd[k] = ks[k]; vd[k] = vs[k]; }
        }
        __syncthreads();

        // ---- S = Q K^T (unscaled) ----
        float Sacc[2][8][4] = {};
#pragma unroll
        for (int kk = 0; kk < 4; kk++) {
            int kb = kk << 4;
            uint32_t A0[4], A1[4];
            ldsm_x4_t(A0, qA + kb * QSTR);
            ldsm_x4_t(A1, qA + kb * QSTR + 16);
#pragma unroll
            for (int ntp = 0; ntp < 4; ntp++) {
                uint32_t Bv[4];
                ldsm_x4_t(Bv, kB + kb * KSTR + ntp * 16);
                mma_f16(Sacc[0][2 * ntp], A0, Bv);
                mma_f16(Sacc[1][2 * ntp], A1, Bv);
                mma_f16(Sacc[0][2 * ntp + 1], A0, Bv + 2);
                mma_f16(Sacc[1][2 * ntp + 1], A1, Bv + 2);
            }
        }

        // ---- online softmax (exp2 domain, scale folded) ----
#pragma unroll
        for (int mt = 0; mt < 2; mt++) {
#pragma unroll
            for (int hi = 0; hi < 2; hi++) {
                int s = mt * 2 + hi;
                float rowmax = -1e30f;
#pragma unroll
                for (int nt = 0; nt < 8; nt++)
                    rowmax = fmaxf(rowmax, fmaxf(Sacc[mt][nt][hi * 2],
                                                 Sacc[mt][nt][hi * 2 + 1]));
                rowmax = fmaxf(rowmax, __shfl_xor_sync(0xffffffffu, rowmax, 1));
                rowmax = fmaxf(rowmax, __shfl_xor_sync(0xffffffffu, rowmax, 2));
                float mnew = fmaxf(mrow[s], rowmax);
                float f = ex2f((mrow[s] - mnew) * SC);
                float sum = 0.f;
                int il = mt * 16 + hi * 8 + lg;
#pragma unroll
                for (int nt = 0; nt < 8; nt++) {
                    float p0 = ex2f((Sacc[mt][nt][hi * 2 + 0] - mnew) * SC);
                    float p1 = ex2f((Sacc[mt][nt][hi * 2 + 1] - mnew) * SC);
                    sum += p0 + p1;
                    __half2 h2;
                    h2.x = __float2half_rn(p0);
                    h2.y = __float2half_rn(p1);
                    *(__half2*)(Pw + il * PSTR + nt * 8 + 2 * lq) = h2;
                    Oacc[mt][nt][hi * 2 + 0] *= f;
                    Oacc[mt][nt][hi * 2 + 1] *= f;
                }
                sum += __shfl_xor_sync(0xffffffffu, sum, 1);
                sum += __shfl_xor_sync(0xffffffffu, sum, 2);
                lrow[s] = lrow[s] * f + sum;
                mrow[s] = mnew;
            }
        }
        __syncwarp();

        // ---- O += P V ----
#pragma unroll
        for (int kk = 0; kk < 4; kk++) {
            int kb = kk << 4;
            uint32_t A0[4], A1[4];
            ldsm_x4(A0, pA + kb);
            ldsm_x4(A1, pA + 16 * PSTR + kb);
#pragma unroll
            for (int ntp = 0; ntp < 4; ntp++) {
                uint32_t Bv[4];
                ldsm_x4(Bv, vB + ntp * 16 * VSTR + kb);
                mma_f16(Oacc[0][2 * ntp], A0, Bv);
                mma_f16(Oacc[1][2 * ntp], A1, Bv);
                mma_f16(Oacc[0][2 * ntp + 1], A0, Bv + 2);
                mma_f16(Oacc[1][2 * ntp + 1], A1, Bv + 2);
            }
        }
        __syncwarp();
    }

    // ---- epilogue: normalize, stage fp32 in smem, coalesced store ----
    __syncthreads();
    float* stg = (float*)smb + warp * (32 * 65);
#pragma unroll
    for (int mt = 0; mt < 2; mt++) {
#pragma unroll
        for (int hi = 0; hi < 2; hi++) {
            float inv = 1.0f / lrow[mt * 2 + hi];
            int il = mt * 16 + hi * 8 + lg;
#pragma unroll
            for (int nt = 0; nt < 8; nt++) {
                stg[il * 65 + nt * 8 + 2 * lq + 0] = Oacc[mt][nt][hi * 2 + 0] * inv;
                stg[il * 65 + nt * 8 + 2 * lq + 1] = Oacc[mt][nt][hi * 2 + 1] * inv;
            }
        }
    }
    __syncwarp();
    {
        float* ob = g_ao + ((size_t)b * C_ + hh * DH_) * N_ + qbase + warp * 32 + lane;
#pragma unroll
        for (int d = 0; d < 64; d++)
            ob[(size_t)d * N_] = stg[lane * 65 + d];
    }
}

// ---------------------------------------------------------------------------
extern "C" void kernel_launch(void* const* d_in, const int* in_sizes, int n_in,
                              void* d_out, int out_size) {
    const float* x      = (const float*)d_in[0];
    const float* gn_w   = (const float*)d_in[1];
    const float* gn_b   = (const float*)d_in[2];
    const float* w_qkv  = (const float*)d_in[3];
    const float* b_qkv  = (const float*)d_in[4];
    const float* w_proj = (const float*)d_in[5];
    const float* b_proj = (const float*)d_in[6];
    float* out = (float*)d_out;

    cudaFuncSetAttribute(attn_kernel,
                         cudaFuncAttributeMaxDynamicSharedMemorySize, ATTN_SMEM);

    gn_kernel<<<B_ * 8, 256>>>(x, gn_w, gn_b);
    gemm_kernel<0><<<dim3(N_ / 128, 768 / 128, B_), 256>>>(w_qkv, b_qkv,
                                                           nullptr, nullptr);
    attn_kernel<<<dim3(N_ / 128, NH_, B_), 128, ATTN_SMEM>>>();
    gemm_kernel<1><<<dim3(N_ / 128, C_ / 128, B_), 256>>>(w_proj, b_proj, x, out);
}

// round 6
// speedup vs baseline: 6.2029x; 1.4684x over previous
#include <cuda_runtime.h>
#include <cuda_fp16.h>
#include <cstdint>

#define B_ 4
#define C_ 256
#define N_ 4096
#define NH_ 4
#define DH_ 64
#define CPG_ 32

// Scratch (device globals — referenced ONLY from device code)
__device__ __half g_qkvh[B_ * 3 * C_ * N_];  // qkv out (fp16)
__device__ __half g_aoh[B_ * C_ * N_];       // attention out (fp16)
__device__ float2 g_part[32][8];             // GN partial sums
__device__ float2 g_gn[32];                  // (mu, rstd) per b*8+g

// ---------------------------------------------------------------------------
// helpers
// ---------------------------------------------------------------------------
__device__ __forceinline__ float ex2f(float x) {
    float y;
    asm("ex2.approx.ftz.f32 %0, %1;" : "=f"(y) : "f"(x));
    return y;
}
__device__ __forceinline__ uint32_t h2ex2(uint32_t x) {
    uint32_t y;
    asm("ex2.approx.f16x2 %0, %1;" : "=r"(y) : "r"(x));
    return y;
}
__device__ __forceinline__ void mma_f16(float* d, const uint32_t* a,
                                        const uint32_t* b) {
    asm volatile(
        "mma.sync.aligned.m16n8k16.row.col.f32.f16.f16.f32 "
        "{%0,%1,%2,%3}, {%4,%5,%6,%7}, {%8,%9}, {%0,%1,%2,%3};"
        : "+f"(d[0]), "+f"(d[1]), "+f"(d[2]), "+f"(d[3])
        : "r"(a[0]), "r"(a[1]), "r"(a[2]), "r"(a[3]), "r"(b[0]), "r"(b[1]));
}
__device__ __forceinline__ void ldsm_x4(uint32_t* r, const void* p) {
    uint32_t a = (uint32_t)__cvta_generic_to_shared(p);
    asm volatile(
        "ldmatrix.sync.aligned.m8n8.x4.shared.b16 {%0,%1,%2,%3}, [%4];"
        : "=r"(r[0]), "=r"(r[1]), "=r"(r[2]), "=r"(r[3]) : "r"(a));
}
__device__ __forceinline__ void ldsm_x4_t(uint32_t* r, const void* p) {
    uint32_t a = (uint32_t)__cvta_generic_to_shared(p);
    asm volatile(
        "ldmatrix.sync.aligned.m8n8.x4.trans.shared.b16 {%0,%1,%2,%3}, [%4];"
        : "=r"(r[0]), "=r"(r[1]), "=r"(r[2]), "=r"(r[3]) : "r"(a));
}
__device__ __forceinline__ void cp16(uint32_t dst, const void* src) {
    asm volatile("cp.async.ca.shared.global [%0], [%1], 16;" ::
                 "r"(dst), "l"(src));
}
#define CP_COMMIT() asm volatile("cp.async.commit_group;")
#define CP_WAIT(n) asm volatile("cp.async.wait_group %0;" :: "n"(n))

// ---------------------------------------------------------------------------
// GroupNorm stats (two-stage, deterministic)
// ---------------------------------------------------------------------------
__global__ void gn_stats1(const float* __restrict__ x) {
    int bg = blockIdx.x >> 3, sl = blockIdx.x & 7;
    const float* xp = x + (size_t)bg * CPG_ * N_ + sl * 16384;
    float s = 0.f, ss = 0.f;
    for (int i = threadIdx.x * 4; i < 16384; i += 1024) {
        float4 v = *(const float4*)(xp + i);
        s += v.x + v.y + v.z + v.w;
        ss += v.x * v.x + v.y * v.y + v.z * v.z + v.w * v.w;
    }
#pragma unroll
    for (int o = 16; o; o >>= 1) {
        s += __shfl_xor_sync(0xffffffffu, s, o);
        ss += __shfl_xor_sync(0xffffffffu, ss, o);
    }
    __shared__ float rs[8], rss[8];
    int wid = threadIdx.x >> 5;
    if ((threadIdx.x & 31) == 0) { rs[wid] = s; rss[wid] = ss; }
    __syncthreads();
    if (threadIdx.x == 0) {
        float S = 0.f, SS = 0.f;
#pragma unroll
        for (int w = 0; w < 8; w++) { S += rs[w]; SS += rss[w]; }
        g_part[bg][sl] = make_float2(S, SS);
    }
}
__global__ void gn_stats2() {
    int g = threadIdx.x;
    if (g < 32) {
        float s = 0.f, ss = 0.f;
#pragma unroll
        for (int i = 0; i < 8; i++) {
            float2 p = g_part[g][i];
            s += p.x; ss += p.y;
        }
        float mu = s / 131072.f;
        float var = ss / 131072.f - mu * mu;
        g_gn[g] = make_float2(mu, rsqrtf(var + 1e-5f));
    }
}

// ---------------------------------------------------------------------------
// fp16 tensor-core GEMM: C[o][n] = sum_c W[o][c] * H[c][n] (+bias)(+res)
// Block 128x128, K=256 in chunks of 32, 256 threads = 8 warps, warp 32x64.
// MODE 0: H = GN(x) computed on load (affine fused), out -> g_qkvh (fp16)
// MODE 1: H = g_aoh (fp16 device symbol), out -> fp32 outf + bias + residual
// ---------------------------------------------------------------------------
#define ASTR 40
#define BSTR 136
template <int MODE>
__global__ void __launch_bounds__(256) gemm_kernel(
    const float* __restrict__ W, const float* __restrict__ bias,
    const float* __restrict__ xin, const float* __restrict__ xres,
    float* __restrict__ outf,
    const float* __restrict__ gnw, const float* __restrict__ gnb) {
    __shared__ __half As[128 * ASTR];
    __shared__ __half Bs[32 * BSTR];
    int b = blockIdx.z;
    int ot = blockIdx.y << 7, nt0 = blockIdx.x << 7;
    int tid = threadIdx.x;
    int warp = tid >> 5, lane = tid & 31, lg = lane >> 2, lq = lane & 3;
    int Mb = (warp >> 1) << 5, Nb = (warp & 1) << 6;

    float acc[2][8][4] = {};
    int cB = tid >> 3, npB = (tid & 7) << 4;

    for (int k0 = 0; k0 < C_; k0 += 32) {
        __syncthreads();
        {   // A tile: W[ot..+128][k0..+32] -> As[o][k] fp16
            int o = tid >> 1, part = (tid & 1) << 4;
            const float4* src =
                (const float4*)(W + (size_t)(ot + o) * C_ + k0 + part);
            __half2 tmp[8];
#pragma unroll
            for (int j = 0; j < 4; j++) {
                float4 v = src[j];
                tmp[2 * j]     = __floats2half2_rn(v.x, v.y);
                tmp[2 * j + 1] = __floats2half2_rn(v.z, v.w);
            }
            *(uint4*)&As[o * ASTR + part]     = *(uint4*)tmp;
            *(uint4*)&As[o * ASTR + part + 8] = *(uint4*)(tmp + 4);
        }
        if (MODE == 0) {  // B tile: GN affine on x
            int c = k0 + cB;
            float2 st = g_gn[b * 8 + (c >> 5)];
            float sc = gnw[c] * st.y;
            float sh = gnb[c] - st.x * sc;
            const float4* src =
                (const float4*)(xin + ((size_t)b * C_ + c) * N_ + nt0 + npB);
            __half2 tmp[8];
#pragma unroll
            for (int j = 0; j < 4; j++) {
                float4 v = src[j];
                tmp[2 * j]     = __floats2half2_rn(v.x * sc + sh, v.y * sc + sh);
                tmp[2 * j + 1] = __floats2half2_rn(v.z * sc + sh, v.w * sc + sh);
            }
            *(uint4*)&Bs[cB * BSTR + npB]     = *(uint4*)tmp;
            *(uint4*)&Bs[cB * BSTR + npB + 8] = *(uint4*)(tmp + 4);
        } else {          // B tile: straight fp16 copy of g_aoh
            const uint4* src =
                (const uint4*)(g_aoh + ((size_t)b * C_ + k0 + cB) * N_ + nt0 + npB);
            *(uint4*)&Bs[cB * BSTR + npB]     = src[0];
            *(uint4*)&Bs[cB * BSTR + npB + 8] = src[1];
        }
        __syncthreads();
#pragma unroll
        for (int kk2 = 0; kk2 < 2; kk2++) {
            uint32_t A[2][4];
            const __half* aA = As + (Mb + (lane & 15)) * ASTR + kk2 * 16 +
                               ((lane >> 4) << 3);
            ldsm_x4(A[0], aA);
            ldsm_x4(A[1], aA + 16 * ASTR);
#pragma unroll
            for (int ntp = 0; ntp < 4; ntp++) {
                uint32_t Bv[4];
                const __half* bB = Bs + (kk2 * 16 + (lane & 15)) * BSTR + Nb +
                                   ntp * 16 + ((lane >> 4) << 3);
                ldsm_x4_t(Bv, bB);
                mma_f16(acc[0][2 * ntp], A[0], Bv);
                mma_f16(acc[1][2 * ntp], A[1], Bv);
                mma_f16(acc[0][2 * ntp + 1], A[0], Bv + 2);
                mma_f16(acc[1][2 * ntp + 1], A[1], Bv + 2);
            }
        }
    }

    // Epilogue
#pragma unroll
    for (int mt = 0; mt < 2; mt++) {
#pragma unroll
        for (int hi = 0; hi < 2; hi++) {
            int o = ot + Mb + mt * 16 + lg + hi * 8;
            float bo = bias[o];
#pragma unroll
            for (int nt = 0; nt < 8; nt++) {
                int n = nt0 + Nb + nt * 8 + 2 * lq;
                float v0 = acc[mt][nt][hi * 2 + 0] + bo;
                float v1 = acc[mt][nt][hi * 2 + 1] + bo;
                if (MODE == 0) {
                    *(__half2*)(g_qkvh + ((size_t)b * 768 + o) * N_ + n) =
                        __floats2half2_rn(v0, v1);
                } else {
                    size_t idx = ((size_t)b * C_ + o) * N_ + n;
                    float2 xr = *(const float2*)(xres + idx);
                    *(float2*)(outf + idx) = make_float2(v0 + xr.x, v1 + xr.y);
                }
            }
        }
    }
}

// ---------------------------------------------------------------------------
// Flash attention, fp16 mma + ldmatrix, register-resident P, cp.async x2.
// Block: (b, h, 128-q tile), 4 warps x 32 rows. K-tiles of 64 keys.
// Smem: Qs[64 d][136 i] + 2x Ks[64 d][72 j] + 2x Vs[64 d][72 j] = 54272 B
// ---------------------------------------------------------------------------
#define QSTR 136
#define KSTR 72
#define VSTR 72
#define KVBYTES (64 * KSTR * 2)  // 9216
#define ATTN_SMEM ((64 * QSTR) * 2 + 4 * KVBYTES)

__global__ void __launch_bounds__(128, 2) attn_kernel() {
    extern __shared__ __half smb[];
    __half* Qs = smb;
    __half* Ks = Qs + 64 * QSTR;           // 2 buffers
    __half* Vs = Ks + 2 * 64 * KSTR;       // 2 buffers

    int b = blockIdx.z, hh = blockIdx.y;
    int qbase = blockIdx.x << 7;
    const __half* qp = g_qkvh + ((size_t)b * 768 + hh * DH_) * N_;
    const __half* kp = qp + (size_t)256 * N_;
    const __half* vp = qp + (size_t)512 * N_;

    int tid = threadIdx.x;
    int warp = tid >> 5, lane = tid & 31, lg = lane >> 2, lq = lane & 3;

    uint32_t ks_sh = (uint32_t)__cvta_generic_to_shared(Ks);
    uint32_t vs_sh = (uint32_t)__cvta_generic_to_shared(Vs);
    int ld_d = tid >> 1, ld_jh = (tid & 1) << 5;

    // Fragment base offsets (proven round-5 recipes)
    int arow = (lane & 7) | ((lane & 16) >> 1);
    int acol = lane & 8;
    const __half* qA = Qs + arow * QSTR + warp * 32 + acol;
    const __half* kB0 = Ks + (lane & 15) * KSTR + ((lane >> 4) << 3);
    int vrow = (lane & 7) | ((lane & 16) >> 1);
    int vcol = lane & 8;
    const __half* vB0 = Vs + vrow * VSTR + vcol;

    // Load Q tile (plain copy, [d][i])
    {
        const uint4* src = (const uint4*)(qp + (size_t)ld_d * N_ + qbase +
                                          (ld_jh << 1));
        uint4* dst = (uint4*)(Qs + ld_d * QSTR + (ld_jh << 1));
#pragma unroll
        for (int k = 0; k < 8; k++) dst[k] = src[k];
    }
    // Prefetch K/V tile 0 into buffer 0
    {
        const __half* ksrc = kp + (size_t)ld_d * N_ + ld_jh;
        const __half* vsrc = vp + (size_t)ld_d * N_ + ld_jh;
        uint32_t kd = ks_sh + (ld_d * KSTR + ld_jh) * 2;
        uint32_t vd = vs_sh + (ld_d * VSTR + ld_jh) * 2;
#pragma unroll
        for (int k = 0; k < 4; k++) {
            cp16(kd + 16 * k, ksrc + 8 * k);
            cp16(vd + 16 * k, vsrc + 8 * k);
        }
        CP_COMMIT();
    }

    float Oacc[2][8][4] = {};
    float mrow[4], lrow[4];
#pragma unroll
    for (int s = 0; s < 4; s++) { mrow[s] = -1e30f; lrow[s] = 0.f; }
    const float SC = 0.125f * 1.4426950408889634f;  // 1/sqrt(dh) * log2(e)

    for (int kt = 0; kt < 64; kt++) {
        int buf = kt & 1;
        if (kt < 63) {  // prefetch next tile into buf^1
            int nb = buf ^ 1;
            const __half* ksrc = kp + (size_t)ld_d * N_ + (kt + 1) * 64 + ld_jh;
            const __half* vsrc = vp + (size_t)ld_d * N_ + (kt + 1) * 64 + ld_jh;
            uint32_t kd = ks_sh + nb * KVBYTES + (ld_d * KSTR + ld_jh) * 2;
            uint32_t vd = vs_sh + nb * KVBYTES + (ld_d * VSTR + ld_jh) * 2;
#pragma unroll
            for (int k = 0; k < 4; k++) {
                cp16(kd + 16 * k, ksrc + 8 * k);
                cp16(vd + 16 * k, vsrc + 8 * k);
            }
            CP_COMMIT();
            CP_WAIT(1);
        } else {
            CP_WAIT(0);
        }
        __syncthreads();

        const __half* kB = kB0 + buf * (64 * KSTR);
        const __half* vB = vB0 + buf * (64 * VSTR);

        // ---- S = Q K^T (unscaled) ----
        float Sacc[2][8][4] = {};
#pragma unroll
        for (int kk = 0; kk < 4; kk++) {
            int kb = kk << 4;
            uint32_t A0[4], A1[4];
            ldsm_x4_t(A0, qA + kb * QSTR);
            ldsm_x4_t(A1, qA + kb * QSTR + 16);
#pragma unroll
            for (int ntp = 0; ntp < 4; ntp++) {
                uint32_t Bv[4];
                ldsm_x4_t(Bv, kB + kb * KSTR + ntp * 16);
                mma_f16(Sacc[0][2 * ntp], A0, Bv);
                mma_f16(Sacc[1][2 * ntp], A1, Bv);
                mma_f16(Sacc[0][2 * ntp + 1], A0, Bv + 2);
                mma_f16(Sacc[1][2 * ntp + 1], A1, Bv + 2);
            }
        }

        // ---- online softmax -> P in registers (fp16 pairs) ----
        uint32_t Ph[2][8][2];
#pragma unroll
        for (int mt = 0; mt < 2; mt++) {
#pragma unroll
            for (int hi = 0; hi < 2; hi++) {
                int s = mt * 2 + hi;
                float rowmax = -1e30f;
#pragma unroll
                for (int nt = 0; nt < 8; nt++)
                    rowmax = fmaxf(rowmax, fmaxf(Sacc[mt][nt][hi * 2],
                                                 Sacc[mt][nt][hi * 2 + 1]));
                rowmax = fmaxf(rowmax, __shfl_xor_sync(0xffffffffu, rowmax, 1));
                rowmax = fmaxf(rowmax, __shfl_xor_sync(0xffffffffu, rowmax, 2));
                float mnew = fmaxf(mrow[s], rowmax);
                float f = ex2f((mrow[s] - mnew) * SC);
                float sum = 0.f;
#pragma unroll
                for (int nt = 0; nt < 8; nt++) {
                    float v0 = (Sacc[mt][nt][hi * 2 + 0] - mnew) * SC;
                    float v1 = (Sacc[mt][nt][hi * 2 + 1] - mnew) * SC;
                    __half2 hv = __floats2half2_rn(v0, v1);
                    uint32_t pe = h2ex2(*(uint32_t*)&hv);
                    Ph[mt][nt][hi] = pe;
                    float2 pf = __half22float2(*(__half2*)&pe);
                    sum += pf.x + pf.y;
                    Oacc[mt][nt][hi * 2 + 0] *= f;
                    Oacc[mt][nt][hi * 2 + 1] *= f;
                }
                sum += __shfl_xor_sync(0xffffffffu, sum, 1);
                sum += __shfl_xor_sync(0xffffffffu, sum, 2);
                lrow[s] = lrow[s] * f + sum;
                mrow[s] = mnew;
            }
        }

        // ---- O += P V  (P stays in registers: C-frag == A-frag layout) ----
#pragma unroll
        for (int kk = 0; kk < 4; kk++) {
            uint32_t A0[4] = {Ph[0][2 * kk][0], Ph[0][2 * kk][1],
                              Ph[0][2 * kk + 1][0], Ph[0][2 * kk + 1][1]};
            uint32_t A1[4] = {Ph[1][2 * kk][0], Ph[1][2 * kk][1],
                              Ph[1][2 * kk + 1][0], Ph[1][2 * kk + 1][1]};
#pragma unroll
            for (int ntp = 0; ntp < 4; ntp++) {
                uint32_t Bv[4];
                ldsm_x4(Bv, vB + ntp * 16 * VSTR + kk * 16);
                mma_f16(Oacc[0][2 * ntp], A0, Bv);
                mma_f16(Oacc[1][2 * ntp], A1, Bv);
                mma_f16(Oacc[0][2 * ntp + 1], A0, Bv + 2);
                mma_f16(Oacc[1][2 * ntp + 1], A1, Bv + 2);
            }
        }
        __syncthreads();  // all warps done with buf before it is refilled
    }

    // ---- epilogue: normalize, stage fp16, transpose-store to g_aoh ----
    __half* stg = smb + warp * (32 * 66);
#pragma unroll
    for (int mt = 0; mt < 2; mt++) {
#pragma unroll
        for (int hi = 0; hi < 2; hi++) {
            float inv = 1.0f / lrow[mt * 2 + hi];
            int il = mt * 16 + hi * 8 + lg;
#pragma unroll
            for (int nt = 0; nt < 8; nt++) {
                *(__half2*)&stg[il * 66 + nt * 8 + 2 * lq] =
                    __floats2half2_rn(Oacc[mt][nt][hi * 2 + 0] * inv,
                                      Oacc[mt][nt][hi * 2 + 1] * inv);
            }
        }
    }
    __syncwarp();
    {
        __half* ob = g_aoh + ((size_t)b * C_ + hh * DH_) * N_ + qbase +
                     warp * 32 + lane;
#pragma unroll
        for (int d = 0; d < 64; d++)
            ob[(size_t)d * N_] = stg[lane * 66 + d];
    }
}

// ---------------------------------------------------------------------------
extern "C" void kernel_launch(void* const* d_in, const int* in_sizes, int n_in,
                              void* d_out, int out_size) {
    const float* x      = (const float*)d_in[0];
    const float* gn_w   = (const float*)d_in[1];
    const float* gn_b   = (const float*)d_in[2];
    const float* w_qkv  = (const float*)d_in[3];
    const float* b_qkv  = (const float*)d_in[4];
    const float* w_proj = (const float*)d_in[5];
    const float* b_proj = (const float*)d_in[6];
    float* out = (float*)d_out;

    cudaFuncSetAttribute(attn_kernel,
                         cudaFuncAttributeMaxDynamicSharedMemorySize, ATTN_SMEM);

    gn_stats1<<<256, 256>>>(x);
    gn_stats2<<<1, 32>>>();
    gemm_kernel<0><<<dim3(32, 6, 4), 256>>>(w_qkv, b_qkv, x, nullptr, nullptr,
                                            gn_w, gn_b);
    attn_kernel<<<dim3(32, NH_, 4), 128, ATTN_SMEM>>>();
    gemm_kernel<1><<<dim3(32, 2, 4), 256>>>(w_proj, b_proj, nullptr, x, out,
                                            nullptr, nullptr);
}